// round 5
// baseline (speedup 1.0000x reference)
#include <cuda_runtime.h>

#define F_TOTAL 256
#define H 16
#define BATCH 32768
#define GF 16                    // features per CTA
#define NGROUPS (F_TOTAL / GF)   // 16
#define TPB 128
#define RB 4                     // batch rows per thread

typedef unsigned long long u64;

// ---- f32x2 packed helpers (sm_103a) ----
__device__ __forceinline__ u64 pack2(float lo, float hi) {
    u64 r;
    asm("mov.b64 %0, {%1, %2};" : "=l"(r)
        : "r"(__float_as_uint(lo)), "r"(__float_as_uint(hi)));
    return r;
}
__device__ __forceinline__ u64 bcast2(float v) {
    u64 r;
    unsigned u = __float_as_uint(v);
    asm("mov.b64 %0, {%1, %1};" : "=l"(r) : "r"(u));
    return r;
}
__device__ __forceinline__ void ffma2(u64& d, u64 a, u64 b) {
    asm("fma.rn.f32x2 %0, %1, %2, %0;" : "+l"(d) : "l"(a), "l"(b));
}
__device__ __forceinline__ u64 fma2v(u64 a, u64 b, u64 c) {
    u64 d;
    asm("fma.rn.f32x2 %0, %1, %2, %3;" : "=l"(d) : "l"(a), "l"(b), "l"(c));
    return d;
}
__device__ __forceinline__ float lo32(u64 v) {
    return __uint_as_float((unsigned)v);
}
__device__ __forceinline__ float hi32(u64 v) {
    return __uint_as_float((unsigned)(v >> 32));
}
__device__ __forceinline__ u64 relu2(u64 v) {
    return pack2(fmaxf(lo32(v), 0.f), fmaxf(hi32(v), 0.f));
}

__global__ void igann_init_kernel(float* __restrict__ out,
                                  const float* __restrict__ bias_b) {
    int i = blockIdx.x * blockDim.x + threadIdx.x;
    if (i < BATCH) out[i] = bias_b[0];
}

// Half of one feature's fc2 outputs (8 of 16 j's) for RB rows; h1 recomputed.
__device__ __forceinline__ void feature_half(
    int fi, int half, const u64* __restrict__ xdup,
    const ulonglong2* __restrict__ sW1dup,   // [GF*H]   {dup w1, dup b1}
    const ulonglong2* __restrict__ sW2p,     // [GF*H*4] j-pair packed
    const ulonglong2* __restrict__ sB2p,     // [GF*4]   raw-aliased pairs
    const ulonglong2* __restrict__ sW3p,     // [GF*4]   raw-aliased pairs
    u64* __restrict__ oA)                    // [RB] packed partial sums
{
    const ulonglong2* w1p = sW1dup + fi * H;
    const ulonglong2* w2p = sW2p + fi * (H * 4) + 2 * half;

    u64 acc[RB][4];

    // i = 0 peel: init accumulators with b2 via 3-operand fma2
    {
        ulonglong2 wb = w1p[0];
        u64 hd[RB];
        #pragma unroll
        for (int r = 0; r < RB; r++)
            hd[r] = relu2(fma2v(xdup[r], wb.x, wb.y));
        #pragma unroll
        for (int ql = 0; ql < 2; ql++) {
            ulonglong2 w  = w2p[ql];
            ulonglong2 bv = sB2p[fi * 4 + 2 * half + ql];
            #pragma unroll
            for (int r = 0; r < RB; r++) {
                acc[r][2 * ql]     = fma2v(w.x, hd[r], bv.x);
                acc[r][2 * ql + 1] = fma2v(w.y, hd[r], bv.y);
            }
        }
    }
    #pragma unroll 5
    for (int i = 1; i < H; i++) {
        ulonglong2 wb = w1p[i];
        u64 hd[RB];
        #pragma unroll
        for (int r = 0; r < RB; r++)
            hd[r] = relu2(fma2v(xdup[r], wb.x, wb.y));
        #pragma unroll
        for (int ql = 0; ql < 2; ql++) {
            ulonglong2 w = w2p[i * 4 + ql];
            #pragma unroll
            for (int r = 0; r < RB; r++) {
                ffma2(acc[r][2 * ql],     w.x, hd[r]);
                ffma2(acc[r][2 * ql + 1], w.y, hd[r]);
            }
        }
    }
    // fc3 partial: relu(h2_half) . W3_half
    #pragma unroll
    for (int ql = 0; ql < 2; ql++) {
        ulonglong2 w3 = sW3p[fi * 4 + 2 * half + ql];
        #pragma unroll
        for (int r = 0; r < RB; r++) {
            ffma2(oA[r], relu2(acc[r][2 * ql]),     w3.x);
            ffma2(oA[r], relu2(acc[r][2 * ql + 1]), w3.y);
        }
    }
}

__global__ __launch_bounds__(TPB, 5) void igann_kernel(
    const float* __restrict__ x,   // [B, F]
    const float* __restrict__ la,  // [F]
    const float* __restrict__ W1,  // [F, H]
    const float* __restrict__ b1,  // [F, H]
    const float* __restrict__ W2,  // [F, H(out), H(in)]
    const float* __restrict__ b2,  // [F, H]
    const float* __restrict__ W3,  // [F, H]
    const float* __restrict__ b3,  // [F]
    float* __restrict__ out)       // [B]
{
    __shared__ ulonglong2 sW1dup[GF * H];   // 4 KB  {dup w1, dup b1}
    __shared__ ulonglong2 sW2p[GF * H * 4]; // 16 KB j-pair packed W2^T
    __shared__ ulonglong2 sB2p[GF * 4];     // raw b2 rows pair-aliased
    __shared__ ulonglong2 sW3p[GF * 4];     // raw W3 rows pair-aliased
    __shared__ u64 sA0[GF];                 // {a, 0}
    __shared__ float sB3sum;

    const int g   = blockIdx.y;
    const int tid = threadIdx.x;
    const int f0  = g * GF;

    // ---- stage weights ----
    #pragma unroll
    for (int k = 0; k < 8; k++) {
        int e  = tid + k * TPB;       // 0..1023
        int fi = e >> 6;
        int i  = (e >> 2) & 15;
        int q  = e & 3;
        const float* wp = W2 + (size_t)(f0 + fi) * (H * H) + i;
        ulonglong2 v;
        v.x = pack2(wp[(4 * q + 0) * H], wp[(4 * q + 1) * H]);
        v.y = pack2(wp[(4 * q + 2) * H], wp[(4 * q + 3) * H]);
        sW2p[e] = v;
    }
    #pragma unroll
    for (int k = 0; k < 2; k++) {
        int e = tid + k * TPB;        // 0..255 == GF*H
        ulonglong2 v;
        v.x = bcast2(W1[f0 * H + e]);
        v.y = bcast2(b1[f0 * H + e]);
        sW1dup[e] = v;
        ((float*)sB2p)[e] = b2[f0 * H + e];
        ((float*)sW3p)[e] = W3[f0 * H + e];
    }
    if (tid < GF) sA0[tid] = pack2(la[f0 + tid], 0.f);
    if (tid == 0) {
        float s = 0.f;
        #pragma unroll
        for (int f = 0; f < GF; f++) s += b3[f0 + f];
        sB3sum = s;
    }
    __syncthreads();

    // ---- compute: RB rows per thread ----
    const int b0 = blockIdx.x * (TPB * RB) + tid;
    const float* xbase = x + (size_t)b0 * F_TOTAL + f0;

    u64 oA[RB];
    #pragma unroll
    for (int r = 0; r < RB; r++) oA[r] = 0ull;

    #pragma unroll 1       // body = 2 features (each as 2 j-halves)
    for (int o2 = 0; o2 < 8; o2++) {
        float2 xq[RB];
        #pragma unroll
        for (int r = 0; r < RB; r++)
            xq[r] = *(const float2*)(xbase + (size_t)r * TPB * F_TOTAL + o2 * 2);

        #pragma unroll
        for (int sub = 0; sub < 2; sub++) {
            const int fi = o2 * 2 + sub;
            u64 xdup[RB];
            #pragma unroll
            for (int r = 0; r < RB; r++)
                xdup[r] = bcast2(sub ? xq[r].y : xq[r].x);

            feature_half(fi, 0, xdup, sW1dup, sW2p, sB2p, sW3p, oA);
            feature_half(fi, 1, xdup, sW1dup, sW2p, sB2p, sW3p, oA);

            // linear term: {a,0} packed -> adds a*x to lo lane only
            u64 a0 = sA0[fi];
            #pragma unroll
            for (int r = 0; r < RB; r++)
                ffma2(oA[r], a0, xdup[r]);
        }
    }

    const float base = sB3sum;
    #pragma unroll
    for (int r = 0; r < RB; r++)
        atomicAdd(&out[b0 + r * TPB], lo32(oA[r]) + hi32(oA[r]) + base);
}

extern "C" void kernel_launch(void* const* d_in, const int* in_sizes, int n_in,
                              void* d_out, int out_size) {
    const float* x      = (const float*)d_in[0];
    const float* la     = (const float*)d_in[1];
    const float* bias_b = (const float*)d_in[2];
    const float* W1     = (const float*)d_in[3];
    const float* b1     = (const float*)d_in[4];
    const float* W2     = (const float*)d_in[5];
    const float* b2     = (const float*)d_in[6];
    const float* W3     = (const float*)d_in[7];
    const float* b3     = (const float*)d_in[8];
    float* out = (float*)d_out;

    igann_init_kernel<<<BATCH / 256, 256>>>(out, bias_b);

    dim3 grid(BATCH / (TPB * RB), NGROUPS);
    igann_kernel<<<grid, TPB>>>(x, la, W1, b1, W2, b2, W3, b3, out);
}

// round 6
// speedup vs baseline: 1.2342x; 1.2342x over previous
#include <cuda_runtime.h>

#define F_TOTAL 256
#define H 16
#define BATCH 32768
#define GF 16                    // features per CTA
#define NGROUPS (F_TOTAL / GF)   // 16
#define TPB 128
#define RB 4                     // batch rows per thread

typedef unsigned long long u64;

// ---- f32x2 packed helpers (sm_103a) ----
__device__ __forceinline__ u64 pack2(float lo, float hi) {
    u64 r;
    asm("mov.b64 %0, {%1, %2};" : "=l"(r)
        : "r"(__float_as_uint(lo)), "r"(__float_as_uint(hi)));
    return r;
}
__device__ __forceinline__ u64 bcast2(float v) {
    u64 r;
    unsigned u = __float_as_uint(v);
    asm("mov.b64 %0, {%1, %1};" : "=l"(r) : "r"(u));
    return r;
}
__device__ __forceinline__ void ffma2(u64& d, u64 a, u64 b) {
    asm("fma.rn.f32x2 %0, %1, %2, %0;" : "+l"(d) : "l"(a), "l"(b));
}
__device__ __forceinline__ u64 fma2v(u64 a, u64 b, u64 c) {
    u64 d;
    asm("fma.rn.f32x2 %0, %1, %2, %3;" : "=l"(d) : "l"(a), "l"(b), "l"(c));
    return d;
}
__device__ __forceinline__ float lo32(u64 v) {
    return __uint_as_float((unsigned)v);
}
__device__ __forceinline__ float hi32(u64 v) {
    return __uint_as_float((unsigned)(v >> 32));
}
__device__ __forceinline__ u64 relu2(u64 v) {
    return pack2(fmaxf(lo32(v), 0.f), fmaxf(hi32(v), 0.f));
}

__global__ void igann_init_kernel(float* __restrict__ out,
                                  const float* __restrict__ bias_b) {
    int i = blockIdx.x * blockDim.x + threadIdx.x;
    if (i < BATCH) out[i] = bias_b[0];
}

// One feature's full subnet for RB batch rows.
// xdup[r] = {x,x}; W2 j-pair packed (not duplicated); W1/b1 duplicated.
__device__ __forceinline__ void feature_body(
    int fi, const u64* __restrict__ xdup,
    const ulonglong2* __restrict__ sW1dup,   // [GF*H]   {dup w1, dup b1}
    const ulonglong2* __restrict__ sW2p,     // [GF*H*4] j-pair packed
    const ulonglong2* __restrict__ sB2p,     // [GF*4]   raw-aliased pairs
    const ulonglong2* __restrict__ sW3p,     // [GF*4]   raw-aliased pairs
    const u64* __restrict__ sA0,             // [GF]     {a, 0}
    u64* __restrict__ oA)                    // [RB] packed sums
{
    const ulonglong2* w1p = sW1dup + fi * H;
    const ulonglong2* w2p = sW2p + fi * (H * 4);
    const ulonglong2* b2p = sB2p + fi * 4;

    u64 acc[RB][8];

    // i = 0 peel: accumulators initialized via 3-operand fma2 with b2
    {
        ulonglong2 wb = w1p[0];
        u64 hd[RB];
        #pragma unroll
        for (int r = 0; r < RB; r++)
            hd[r] = relu2(fma2v(xdup[r], wb.x, wb.y));
        #pragma unroll
        for (int q = 0; q < 4; q++) {
            ulonglong2 w  = w2p[q];
            ulonglong2 bv = b2p[q];
            #pragma unroll
            for (int r = 0; r < RB; r++) {
                acc[r][2 * q]     = fma2v(w.x, hd[r], bv.x);
                acc[r][2 * q + 1] = fma2v(w.y, hd[r], bv.y);
            }
        }
    }
    #pragma unroll
    for (int i = 1; i < H; i++) {
        ulonglong2 wb = w1p[i];
        u64 hd[RB];
        #pragma unroll
        for (int r = 0; r < RB; r++)
            hd[r] = relu2(fma2v(xdup[r], wb.x, wb.y));
        #pragma unroll
        for (int q = 0; q < 4; q++) {
            ulonglong2 w = w2p[i * 4 + q];
            #pragma unroll
            for (int r = 0; r < RB; r++) {
                ffma2(acc[r][2 * q],     w.x, hd[r]);
                ffma2(acc[r][2 * q + 1], w.y, hd[r]);
            }
        }
    }
    // fc3: relu(h2) . W3, j-pair packed
    #pragma unroll
    for (int q = 0; q < 4; q++) {
        ulonglong2 w3 = sW3p[fi * 4 + q];
        #pragma unroll
        for (int r = 0; r < RB; r++) {
            ffma2(oA[r], relu2(acc[r][2 * q]),     w3.x);
            ffma2(oA[r], relu2(acc[r][2 * q + 1]), w3.y);
        }
    }
    // linear term: {a,0} packed adds a*x to the lo lane only
    u64 a0 = sA0[fi];
    #pragma unroll
    for (int r = 0; r < RB; r++)
        ffma2(oA[r], a0, xdup[r]);
}

__global__ __launch_bounds__(TPB, 3) void igann_kernel(
    const float* __restrict__ x,   // [B, F]
    const float* __restrict__ la,  // [F]
    const float* __restrict__ W1,  // [F, H]
    const float* __restrict__ b1,  // [F, H]
    const float* __restrict__ W2,  // [F, H(out), H(in)]
    const float* __restrict__ b2,  // [F, H]
    const float* __restrict__ W3,  // [F, H]
    const float* __restrict__ b3,  // [F]
    float* __restrict__ out)       // [B]
{
    __shared__ ulonglong2 sW1dup[GF * H];   // 4 KB  {dup w1, dup b1}
    __shared__ ulonglong2 sW2p[GF * H * 4]; // 16 KB j-pair packed W2^T
    __shared__ ulonglong2 sB2p[GF * 4];     // raw b2 rows pair-aliased
    __shared__ ulonglong2 sW3p[GF * 4];     // raw W3 rows pair-aliased
    __shared__ u64 sA0[GF];                 // {a, 0}
    __shared__ float sB3sum;

    const int g   = blockIdx.y;
    const int tid = threadIdx.x;
    const int f0  = g * GF;

    // ---- stage weights ----
    #pragma unroll
    for (int k = 0; k < 8; k++) {
        int e  = tid + k * TPB;       // 0..1023
        int fi = e >> 6;
        int i  = (e >> 2) & 15;
        int q  = e & 3;
        const float* wp = W2 + (size_t)(f0 + fi) * (H * H) + i;
        ulonglong2 v;
        v.x = pack2(wp[(4 * q + 0) * H], wp[(4 * q + 1) * H]);
        v.y = pack2(wp[(4 * q + 2) * H], wp[(4 * q + 3) * H]);
        sW2p[e] = v;
    }
    #pragma unroll
    for (int k = 0; k < 2; k++) {
        int e = tid + k * TPB;        // 0..255 == GF*H
        ulonglong2 v;
        v.x = bcast2(W1[f0 * H + e]);
        v.y = bcast2(b1[f0 * H + e]);
        sW1dup[e] = v;
        ((float*)sB2p)[e] = b2[f0 * H + e];
        ((float*)sW3p)[e] = W3[f0 * H + e];
    }
    if (tid < GF) sA0[tid] = pack2(la[f0 + tid], 0.f);
    if (tid == 0) {
        float s = 0.f;
        #pragma unroll
        for (int f = 0; f < GF; f++) s += b3[f0 + f];
        sB3sum = s;
    }
    __syncthreads();

    // ---- compute: RB rows per thread ----
    const int b0 = blockIdx.x * (TPB * RB) + tid;
    const float* xbase = x + (size_t)b0 * F_TOTAL + f0;

    u64 oA[RB];
    #pragma unroll
    for (int r = 0; r < RB; r++) oA[r] = 0ull;

    #pragma unroll 1       // body = 2 features
    for (int o2 = 0; o2 < 8; o2++) {
        float2 xq[RB];
        #pragma unroll
        for (int r = 0; r < RB; r++)
            xq[r] = *(const float2*)(xbase + (size_t)r * TPB * F_TOTAL + o2 * 2);

        {
            u64 xdup[RB];
            #pragma unroll
            for (int r = 0; r < RB; r++) xdup[r] = bcast2(xq[r].x);
            feature_body(o2 * 2, xdup, sW1dup, sW2p, sB2p, sW3p, sA0, oA);
        }
        {
            u64 xdup[RB];
            #pragma unroll
            for (int r = 0; r < RB; r++) xdup[r] = bcast2(xq[r].y);
            feature_body(o2 * 2 + 1, xdup, sW1dup, sW2p, sB2p, sW3p, sA0, oA);
        }
    }

    const float base = sB3sum;
    #pragma unroll
    for (int r = 0; r < RB; r++)
        atomicAdd(&out[b0 + r * TPB], lo32(oA[r]) + hi32(oA[r]) + base);
}

extern "C" void kernel_launch(void* const* d_in, const int* in_sizes, int n_in,
                              void* d_out, int out_size) {
    const float* x      = (const float*)d_in[0];
    const float* la     = (const float*)d_in[1];
    const float* bias_b = (const float*)d_in[2];
    const float* W1     = (const float*)d_in[3];
    const float* b1     = (const float*)d_in[4];
    const float* W2     = (const float*)d_in[5];
    const float* b2     = (const float*)d_in[6];
    const float* W3     = (const float*)d_in[7];
    const float* b3     = (const float*)d_in[8];
    float* out = (float*)d_out;

    igann_init_kernel<<<BATCH / 256, 256>>>(out, bias_b);

    dim3 grid(BATCH / (TPB * RB), NGROUPS);
    igann_kernel<<<grid, TPB>>>(x, la, W1, b1, W2, b2, W3, b3, out);
}